// round 3
// baseline (speedup 1.0000x reference)
#include <cuda_runtime.h>
#include <math.h>

#define N_K   256
#define N_T   128
#define N_C   32
#define N_D   10
#define N_SPK 1000000
#define LOG2PI 1.8378770664093453f

// Packed coefficient row per component:
// [0..54]  : quadratic coeffs over upper-tri features s_i*s_j (i<=j): -P_ii/2 on diag, -P_ij off-diag
// [55..64] : linear coeffs (P @ mu)
// [65]     : constant K_c = -0.5*(mu'P mu + logdet + D*log(2pi))
// [66..67] : pad (row stride 68 floats -> 272B, 16B aligned rows)
#define ROW 68

#define MAIN_BLOCK 256
#define MAX_BLOCKS 4096

__device__ float g_W[N_C * ROW];
__device__ float g_prior;
__device__ float g_logpi[N_K * N_T * N_C];   // (k,t,c)-major, 4 MB, L2-resident
__device__ float g_partial[MAX_BLOCKS];

// ---------------------------------------------------------------------------
// Kernel 1: per-component Cholesky -> precision matrix -> packed coefficients,
// plus the closed-form prior/entropy term. One block, tiny.
// ---------------------------------------------------------------------------
__global__ void setup_kernel(const float* __restrict__ means,
                             const float* __restrict__ covs,
                             const float* __restrict__ b_mu,
                             const float* __restrict__ b_log_sig,
                             const float* __restrict__ beta_mu,
                             const float* __restrict__ beta_log_sig) {
    int tid = threadIdx.x;

    if (tid < N_C) {
        const float* cov = covs + tid * N_D * N_D;
        const float* mu  = means + tid * N_D;

        float L[N_D][N_D];
        float logdet = 0.0f;
        // Cholesky (lower)
        for (int j = 0; j < N_D; j++) {
            float sdiag = cov[j * N_D + j];
            for (int k = 0; k < j; k++) sdiag -= L[j][k] * L[j][k];
            float d = sqrtf(sdiag);
            L[j][j] = d;
            logdet += 2.0f * logf(d);
            for (int i = j + 1; i < N_D; i++) {
                float v = cov[i * N_D + j];
                for (int k = 0; k < j; k++) v -= L[i][k] * L[j][k];
                L[i][j] = v / d;
            }
        }
        // Li = L^{-1} (lower triangular)
        float Li[N_D][N_D];
        for (int j = 0; j < N_D; j++) {
            for (int i = 0; i < N_D; i++) {
                if (i < j) { Li[i][j] = 0.0f; continue; }
                float v = (i == j) ? 1.0f : 0.0f;
                for (int k = j; k < i; k++) v -= L[i][k] * Li[k][j];
                Li[i][j] = v / L[i][i];
            }
        }
        // P = Li^T Li = cov^{-1}
        float P[N_D][N_D];
        for (int i = 0; i < N_D; i++)
            for (int j = 0; j < N_D; j++) {
                float v = 0.0f;
                int k0 = (i > j) ? i : j;
                for (int k = k0; k < N_D; k++) v += Li[k][i] * Li[k][j];
                P[i][j] = v;
            }
        // w = P mu, quad = mu' P mu
        float w[N_D], quad = 0.0f;
        for (int i = 0; i < N_D; i++) {
            float v = 0.0f;
            for (int j = 0; j < N_D; j++) v += P[i][j] * mu[j];
            w[i] = v;
            quad += v * mu[i];
        }
        float* Wc = g_W + tid * ROW;
        int u = 0;
        for (int i = 0; i < N_D; i++)
            for (int j = i; j < N_D; j++) {
                Wc[u++] = (i == j) ? (-0.5f * P[i][i]) : (-P[i][j]);
            }
        for (int i = 0; i < N_D; i++) Wc[55 + i] = w[i];
        Wc[65] = -0.5f * (quad + logdet + (float)N_D * LOG2PI);
        Wc[66] = 0.0f; Wc[67] = 0.0f;
    }

    // prior/entropy term: sum(b_log_sig - 0.5*b_mu^2) + sum(beta_log_sig - 0.5*beta_mu^2)
    __shared__ float red[128];
    float acc = 0.0f;
    for (int i = tid; i < N_C; i += 128)
        acc += b_log_sig[i] - 0.5f * b_mu[i] * b_mu[i];
    for (int i = tid; i < N_C * N_T; i += 128)
        acc += beta_log_sig[i] - 0.5f * beta_mu[i] * beta_mu[i];
    red[tid] = acc;
    __syncthreads();
    for (int s2 = 64; s2 > 0; s2 >>= 1) {
        if (tid < s2) red[tid] += red[tid + s2];
        __syncthreads();
    }
    if (tid == 0) g_prior = red[0];
}

// ---------------------------------------------------------------------------
// Kernel 2: log_pi table, (k,t,c)-major. One warp per (k,t); lane = component.
// ---------------------------------------------------------------------------
__global__ void logpi_kernel(const float* __restrict__ y,
                             const float* __restrict__ b_mu,
                             const float* __restrict__ beta_mu) {
    int warp = (blockIdx.x * blockDim.x + threadIdx.x) >> 5;
    int lane = threadIdx.x & 31;
    if (warp >= N_K * N_T) return;
    int k = warp >> 7;          // N_T = 128
    int t = warp & (N_T - 1);

    float yv  = __ldg(&y[k * N_T + t]);
    float lam = __ldg(&b_mu[lane]) + __ldg(&beta_mu[lane * N_T + t]) * yv;

    float m = lam;
    #pragma unroll
    for (int o = 16; o > 0; o >>= 1)
        m = fmaxf(m, __shfl_xor_sync(0xffffffffu, m, o));
    float e = __expf(lam - m);
    float ssum = e;
    #pragma unroll
    for (int o = 16; o > 0; o >>= 1)
        ssum += __shfl_xor_sync(0xffffffffu, ssum, o);

    g_logpi[warp * N_C + lane] = lam - m - __logf(ssum);
}

// ---------------------------------------------------------------------------
// Kernel 3: main — thread per spike. 55 shared quadratic features,
// 32 x 65-term dots (4-way accumulator ILP), streaming LSE, block reduce.
// ---------------------------------------------------------------------------
__global__ void __launch_bounds__(MAIN_BLOCK, 2)
main_kernel(const float* __restrict__ s,
            const int*   __restrict__ ks,
            const int*   __restrict__ ts) {
    __shared__ float sW[N_C * ROW];
    __shared__ float sred[MAIN_BLOCK];

    for (int i = threadIdx.x; i < N_C * ROW; i += MAIN_BLOCK)
        sW[i] = g_W[i];
    __syncthreads();

    int n = blockIdx.x * MAIN_BLOCK + threadIdx.x;
    float lse = 0.0f;

    if (n < N_SPK) {
        float sv[N_D];
        #pragma unroll
        for (int i = 0; i < N_D; i++) sv[i] = __ldg(&s[n * N_D + i]);

        float f[55];
        {
            int u = 0;
            #pragma unroll
            for (int i = 0; i < N_D; i++)
                #pragma unroll
                for (int j = i; j < N_D; j++)
                    f[u++] = sv[i] * sv[j];
        }

        int base = (__ldg(&ks[n]) * N_T + __ldg(&ts[n])) * N_C;
        const float* lp = g_logpi + base;

        float m = -1e30f, ssum = 0.0f;
        #pragma unroll 4
        for (int c = 0; c < N_C; c++) {
            const float* wc = &sW[c * ROW];
            float a0 = wc[65], a1 = 0.0f, a2 = 0.0f, a3 = 0.0f;
            #pragma unroll
            for (int j = 0; j < 52; j += 4) {
                a0 = fmaf(wc[j + 0], f[j + 0], a0);
                a1 = fmaf(wc[j + 1], f[j + 1], a1);
                a2 = fmaf(wc[j + 2], f[j + 2], a2);
                a3 = fmaf(wc[j + 3], f[j + 3], a3);
            }
            a0 = fmaf(wc[52], f[52], a0);
            a1 = fmaf(wc[53], f[53], a1);
            a2 = fmaf(wc[54], f[54], a2);
            #pragma unroll
            for (int i = 0; i < N_D; i++) {
                float* aa = (i & 3) == 0 ? &a0 : (i & 3) == 1 ? &a1 : (i & 3) == 2 ? &a2 : &a3;
                *aa = fmaf(wc[55 + i], sv[i], *aa);
            }
            float logit = ((a0 + a1) + (a2 + a3)) + __ldg(&lp[c]);

            float nm = fmaxf(m, logit);
            ssum = ssum * __expf(m - nm) + __expf(logit - nm);
            m = nm;
        }
        lse = m + __logf(ssum);
    }

    sred[threadIdx.x] = lse;
    __syncthreads();
    #pragma unroll
    for (int s2 = MAIN_BLOCK / 2; s2 > 0; s2 >>= 1) {
        if (threadIdx.x < s2) sred[threadIdx.x] += sred[threadIdx.x + s2];
        __syncthreads();
    }
    if (threadIdx.x == 0) g_partial[blockIdx.x] = sred[0];
}

// ---------------------------------------------------------------------------
// Kernel 4: deterministic final reduction (double accumulation).
// ---------------------------------------------------------------------------
__global__ void final_kernel(float* __restrict__ out, int nblocks) {
    __shared__ double dred[256];
    int tid = threadIdx.x;
    double acc = 0.0;
    for (int i = tid; i < nblocks; i += 256) acc += (double)g_partial[i];
    dred[tid] = acc;
    __syncthreads();
    for (int s2 = 128; s2 > 0; s2 >>= 1) {
        if (tid < s2) dred[tid] += dred[tid + s2];
        __syncthreads();
    }
    if (tid == 0) out[0] = (float)(dred[0] + (double)g_prior);
}

// ---------------------------------------------------------------------------
extern "C" void kernel_launch(void* const* d_in, const int* in_sizes, int n_in,
                              void* d_out, int out_size) {
    const float* s            = (const float*)d_in[0];
    const float* y            = (const float*)d_in[1];
    const int*   ks           = (const int*)  d_in[2];
    const int*   ts           = (const int*)  d_in[3];
    const float* means        = (const float*)d_in[4];
    const float* covs         = (const float*)d_in[5];
    const float* b_mu         = (const float*)d_in[6];
    const float* b_log_sig    = (const float*)d_in[7];
    const float* beta_mu      = (const float*)d_in[8];
    const float* beta_log_sig = (const float*)d_in[9];

    setup_kernel<<<1, 128>>>(means, covs, b_mu, b_log_sig, beta_mu, beta_log_sig);

    // 32768 (k,t) warps -> 1,048,576 threads
    logpi_kernel<<<(N_K * N_T * 32) / 256, 256>>>(y, b_mu, beta_mu);

    int nblocks = (N_SPK + MAIN_BLOCK - 1) / MAIN_BLOCK;
    main_kernel<<<nblocks, MAIN_BLOCK>>>(s, ks, ts);

    final_kernel<<<1, 256>>>((float*)d_out, nblocks);
}